// round 14
// baseline (speedup 1.0000x reference)
#include <cuda_runtime.h>
#include <cstdint>

#define N_NODES 10000
#define E_TOTAL 640000
#define D_NODE 128
#define D_EDGE 64
#define D_IN 192
#define D_OUT 128

#define TM 128              // edges per CTA
#define NTHREADS 256        // 8 warps
#define KCH 96              // K chunk
#define A_STRIDE 100        // mod 32 = 4 -> conflict-free A frags
#define W_STRIDE 136        // mod 32 = 8 -> conflict-free B frags
#define EP_STRIDE 132       // epilogue repack stride (words)

#define SMEM_A_WORDS (TM * A_STRIDE)            // 12800
#define SMEM_W_WORDS (KCH * W_STRIDE)           // 13056
#define SMEM_BYTES ((SMEM_A_WORDS + SMEM_W_WORDS) * 4)   // 103424 -> 2 CTAs/SM

__device__ float g_cnt[N_NODES];
__device__ int   g_hist[N_NODES];
__device__ int   g_cursor[N_NODES];
__device__ int   g_perm[E_TOTAL];
__device__ int   g_idx64;

__device__ __forceinline__ uint32_t f2tf32(float f) {
    uint32_t u;
    asm("cvt.rna.tf32.f32 %0, %1;" : "=r"(u) : "f"(f));
    return u;
}
__device__ __forceinline__ void mma_tf32(float* d, const uint32_t* a,
                                         uint32_t b0, uint32_t b1) {
    asm volatile(
        "mma.sync.aligned.m16n8k8.row.col.f32.tf32.tf32.f32 "
        "{%0,%1,%2,%3}, {%4,%5,%6,%7}, {%8,%9}, {%0,%1,%2,%3};"
        : "+f"(d[0]), "+f"(d[1]), "+f"(d[2]), "+f"(d[3])
        : "r"(a[0]), "r"(a[1]), "r"(a[2]), "r"(a[3]), "r"(b0), "r"(b1));
}
__device__ __forceinline__ int clampi(int v, int lo, int hi) {
    return v < lo ? lo : (v > hi ? hi : v);
}
__device__ __forceinline__ int load_dst(const void* ei_raw, int e, int is64) {
    int d;
    if (is64) d = (int)((const long long*)ei_raw)[E_TOTAL + e];
    else      d = ((const int*)ei_raw)[E_TOTAL + e];
    return clampi(d, 0, N_NODES - 1);
}
__device__ __forceinline__ int load_src(const void* ei_raw, int e, int is64) {
    int s;
    if (is64) s = (int)((const long long*)ei_raw)[e];
    else      s = ((const int*)ei_raw)[e];
    return clampi(s, 0, N_NODES - 1);
}

// -------------------------------------------------------------------------
// 1) zero out + hist, sniff dtype
// -------------------------------------------------------------------------
__global__ void zero_kernel(float* __restrict__ out, const unsigned* __restrict__ eiw) {
    int i = blockIdx.x * blockDim.x + threadIdx.x;
    if (i < N_NODES * D_OUT) out[i] = 0.0f;
    if (i < N_NODES) g_hist[i] = 0;
    if (blockIdx.x == 0 && threadIdx.x == 0) {
        int is64 = 1;
        #pragma unroll 1
        for (int k = 0; k < 64; k++) {
            unsigned hi = eiw[2 * k + 1];
            if (hi != 0u && hi != 0xFFFFFFFFu) { is64 = 0; break; }
        }
        g_idx64 = is64;
    }
}

// -------------------------------------------------------------------------
// 2) histogram of dst
// -------------------------------------------------------------------------
__global__ void hist_kernel(const void* __restrict__ ei_raw) {
    int e = blockIdx.x * blockDim.x + threadIdx.x;
    if (e >= E_TOTAL) return;
    atomicAdd(&g_hist[load_dst(ei_raw, e, g_idx64)], 1);
}

// -------------------------------------------------------------------------
// 3) exclusive scan (1 block) -> cursor, float counts
// -------------------------------------------------------------------------
__global__ void scan_kernel() {
    __shared__ int sbuf[1024];
    __shared__ int s_carry;
    const int t = threadIdx.x;
    if (t == 0) s_carry = 0;
    __syncthreads();
    for (int base = 0; base < N_NODES; base += 1024) {
        int n = base + t;
        int v = (n < N_NODES) ? g_hist[n] : 0;
        sbuf[t] = v;
        __syncthreads();
        for (int ofs = 1; ofs < 1024; ofs <<= 1) {
            int add = (t >= ofs) ? sbuf[t - ofs] : 0;
            __syncthreads();
            sbuf[t] += add;
            __syncthreads();
        }
        int inc = sbuf[t] + s_carry;     // inclusive + carry
        if (n < N_NODES) {
            g_cursor[n] = inc - v;       // exclusive offset
            g_cnt[n] = (float)v;
        }
        __syncthreads();
        if (t == 1023) s_carry = inc;
        __syncthreads();
    }
}

// -------------------------------------------------------------------------
// 4) cursor-scatter: dst-sorted edge permutation
// -------------------------------------------------------------------------
__global__ void perm_kernel(const void* __restrict__ ei_raw) {
    int e = blockIdx.x * blockDim.x + threadIdx.x;
    if (e >= E_TOTAL) return;
    int d = load_dst(ei_raw, e, g_idx64);
    int pos = atomicAdd(&g_cursor[d], 1);
    g_perm[pos] = e;
}

// -------------------------------------------------------------------------
// 5) fused gather + tf32 mma.sync GEMM + segmented-reduce scatter
//    CTA: 128 dst-sorted edges x 128 cols, K = 2 chunks of 96.
// -------------------------------------------------------------------------
extern __shared__ uint32_t dsm[];

__global__ void __launch_bounds__(NTHREADS, 2)
gemm_scatter_mma(const float* __restrict__ x,
                 const void* __restrict__ ei_raw,
                 const float* __restrict__ ef,
                 const float* __restrict__ W,
                 float* __restrict__ out)
{
    __shared__ int s_src[TM];
    __shared__ int s_dst[TM];
    __shared__ int s_eid[TM];

    uint32_t* sA = dsm;                      // [TM][A_STRIDE]
    uint32_t* sW = dsm + SMEM_A_WORDS;       // [KCH][W_STRIDE]
    float*    sE = (float*)dsm;              // epilogue repack [TM][EP_STRIDE]

    const int tid = threadIdx.x;
    const int wid = tid >> 5;
    const int lane = tid & 31;
    const int e0 = blockIdx.x * TM;

    if (tid < TM) {
        int is64 = g_idx64;
        int eid = g_perm[e0 + tid];
        s_eid[tid] = eid;
        s_src[tid] = load_src(ei_raw, eid, is64);
        s_dst[tid] = load_dst(ei_raw, eid, is64);
    }

    const int rowband = (wid >> 1) * 32;
    const int colh = (wid & 1) * 64;
    const int lq = lane >> 2;      // 0..7
    const int lr = lane & 3;       // 0..3

    float acc[2][8][4];
#pragma unroll
    for (int m = 0; m < 2; m++)
#pragma unroll
        for (int nt = 0; nt < 8; nt++)
#pragma unroll
            for (int c = 0; c < 4; c++) acc[m][nt][c] = 0.0f;

#pragma unroll 1
    for (int ch = 0; ch < 2; ch++) {
        __syncthreads();   // smem free (also orders s_src on first pass)

        // ---- stage A chunk: 128 rows x 96 cols (24 float4 per row) ----
        #pragma unroll 2
        for (int idx = tid; idx < TM * 24; idx += NTHREADS) {
            int e = idx / 24, q = idx - e * 24;
            float4 v;
            if (ch == 0) {
                v = ((const float4*)(x + (size_t)s_src[e] * D_NODE))[q];
            } else {
                if (q < 8) v = ((const float4*)(x + (size_t)s_src[e] * D_NODE))[24 + q];
                else       v = ((const float4*)(ef + (size_t)s_eid[e] * D_EDGE))[q - 8];
            }
            uint4 t;
            t.x = f2tf32(v.x); t.y = f2tf32(v.y);
            t.z = f2tf32(v.z); t.w = f2tf32(v.w);
            *(uint4*)(sA + e * A_STRIDE + q * 4) = t;
        }
        // ---- stage W chunk: 96 rows x 128 cols ----
        #pragma unroll 2
        for (int idx = tid; idx < KCH * 32; idx += NTHREADS) {
            int k = idx >> 5, nq = idx & 31;
            float4 v = ((const float4*)(W + (size_t)(ch * KCH + k) * D_OUT))[nq];
            uint4 t;
            t.x = f2tf32(v.x); t.y = f2tf32(v.y);
            t.z = f2tf32(v.z); t.w = f2tf32(v.w);
            *(uint4*)(sW + k * W_STRIDE + nq * 4) = t;
        }
        __syncthreads();

        // ---- 12 k-steps of m16n8k8 ----
#pragma unroll
        for (int s = 0; s < KCH / 8; s++) {
            const int kb = s * 8;
            uint32_t a[2][4];
            {
                const uint32_t* pa = sA + (rowband + lq) * A_STRIDE + kb + lr;
                a[0][0] = pa[0];
                a[0][1] = pa[8 * A_STRIDE];
                a[0][2] = pa[4];
                a[0][3] = pa[8 * A_STRIDE + 4];
                a[1][0] = pa[16 * A_STRIDE];
                a[1][1] = pa[24 * A_STRIDE];
                a[1][2] = pa[16 * A_STRIDE + 4];
                a[1][3] = pa[24 * A_STRIDE + 4];
            }
            const uint32_t* pb0 = sW + (kb + lr) * W_STRIDE + colh + lq;
            const uint32_t* pb1 = pb0 + 4 * W_STRIDE;
#pragma unroll
            for (int nt = 0; nt < 8; nt++) {
                uint32_t b0 = pb0[nt * 8];
                uint32_t b1 = pb1[nt * 8];
                mma_tf32(acc[0][nt], a[0], b0, b1);
                mma_tf32(acc[1][nt], a[1], b0, b1);
            }
        }
    }

    // ---- epilogue: repack accumulators to smem ----
    __syncthreads();   // all compute done; safe to overwrite sA/sW
#pragma unroll
    for (int m = 0; m < 2; m++) {
        int r = rowband + m * 16 + lq;
        int cb = colh + 2 * lr;
#pragma unroll
        for (int nt = 0; nt < 8; nt++) {
            sE[r * EP_STRIDE + cb + nt * 8]           = acc[m][nt][0];
            sE[r * EP_STRIDE + cb + nt * 8 + 1]       = acc[m][nt][1];
            sE[(r + 8) * EP_STRIDE + cb + nt * 8]     = acc[m][nt][2];
            sE[(r + 8) * EP_STRIDE + cb + nt * 8 + 1] = acc[m][nt][3];
        }
    }
    __syncthreads();

    // ---- segmented reduction over sorted dst: 1 thread = 1 column x 64 rows ----
    {
        const int c = tid & 127;            // column
        const int h = tid >> 7;             // row half (0/1)
        const int r0 = h * 64;
        float run = 0.0f;
        int prev = s_dst[r0];
        #pragma unroll 4
        for (int r = r0; r < r0 + 64; r++) {
            int d = s_dst[r];
            if (d != prev) {
                atomicAdd(out + (size_t)prev * D_OUT + c, run);
                run = 0.0f;
                prev = d;
            }
            run += sE[r * EP_STRIDE + c];
        }
        atomicAdd(out + (size_t)prev * D_OUT + c, run);
    }
}

// -------------------------------------------------------------------------
__global__ void finalize_kernel(float* __restrict__ out, const float* __restrict__ b) {
    int i = blockIdx.x * blockDim.x + threadIdx.x;
    if (i >= N_NODES * D_OUT) return;
    int node = i >> 7;
    float c = g_cnt[node];
    float v = out[i];
    out[i] = (c > 0.0f) ? (v / c + b[i & (D_OUT - 1)]) : 0.0f;
}

// -------------------------------------------------------------------------
extern "C" void kernel_launch(void* const* d_in, const int* in_sizes, int n_in,
                              void* d_out, int out_size)
{
    const float* x  = (const float*)d_in[0];
    const void*  ei = d_in[1];
    const float* ef = (const float*)d_in[2];
    const float* W  = (const float*)d_in[3];
    const float* b  = (const float*)d_in[4];
    float* out = (float*)d_out;

    cudaFuncSetAttribute(gemm_scatter_mma,
                         cudaFuncAttributeMaxDynamicSharedMemorySize, SMEM_BYTES);

    const int total = N_NODES * D_OUT;
    zero_kernel<<<(total + 255) / 256, 256>>>(out, (const unsigned*)ei);
    hist_kernel<<<(E_TOTAL + 255) / 256, 256>>>(ei);
    scan_kernel<<<1, 1024>>>();
    perm_kernel<<<(E_TOTAL + 255) / 256, 256>>>(ei);
    gemm_scatter_mma<<<E_TOTAL / TM, NTHREADS, SMEM_BYTES>>>(x, ei, ef, W, out);
    finalize_kernel<<<(total + 255) / 256, 256>>>(out, b);
}

// round 16
// speedup vs baseline: 1.3127x; 1.3127x over previous
#include <cuda_runtime.h>
#include <cuda_fp16.h>
#include <cstdint>

#define N_NODES 10000
#define E_TOTAL 640000
#define D_NODE 128
#define D_EDGE 64
#define D_IN 192
#define D_OUT 128

#define TM 256              // edges per CTA
#define NTHREADS 512        // 16 warps
#define KW 96               // K in half2 words (192 halves)
#define A_STRIDE 100        // words; mod 32 = 4 -> conflict-free A frags
#define WP_STRIDE 136       // words; mod 32 = 8 -> conflict-free B frags

#define SMEM_A_WORDS (TM * A_STRIDE)            // 25600
#define SMEM_W_WORDS (KW * WP_STRIDE)           // 13056
#define SMEM_BYTES ((SMEM_A_WORDS + SMEM_W_WORDS) * 4)   // 154624

__device__ float g_cnt[N_NODES];
__device__ int   g_idx64;

__device__ __forceinline__ void mma_f16(float* d, uint32_t a0, uint32_t a1,
                                        uint32_t a2, uint32_t a3,
                                        uint32_t b0, uint32_t b1) {
    asm volatile(
        "mma.sync.aligned.m16n8k16.row.col.f32.f16.f16.f32 "
        "{%0,%1,%2,%3}, {%4,%5,%6,%7}, {%8,%9}, {%0,%1,%2,%3};"
        : "+f"(d[0]), "+f"(d[1]), "+f"(d[2]), "+f"(d[3])
        : "r"(a0), "r"(a1), "r"(a2), "r"(a3), "r"(b0), "r"(b1));
}
__device__ __forceinline__ uint32_t pack2(float lo, float hi) {
    __half2 h = __floats2half2_rn(lo, hi);
    return *(uint32_t*)&h;
}
__device__ __forceinline__ int clampi(int v, int lo, int hi) {
    return v < lo ? lo : (v > hi ? hi : v);
}

// -------------------------------------------------------------------------
__global__ void zero_kernel(float* __restrict__ out, const unsigned* __restrict__ eiw) {
    int i = blockIdx.x * blockDim.x + threadIdx.x;
    if (i < N_NODES * D_OUT) out[i] = 0.0f;
    if (i < N_NODES) g_cnt[i] = 0.0f;
    if (blockIdx.x == 0 && threadIdx.x == 0) {
        int is64 = 1;
        #pragma unroll 1
        for (int k = 0; k < 64; k++) {
            unsigned hi = eiw[2 * k + 1];
            if (hi != 0u && hi != 0xFFFFFFFFu) { is64 = 0; break; }
        }
        g_idx64 = is64;
    }
}

// -------------------------------------------------------------------------
// Fused gather + fp16 m16n8k16 mma.sync GEMM (f32 accum) + scatter-add.
// CTA: 256 edges x 128 cols, single K=192 stage.
// Warp w: rows (w>>1)*32 .. +31, cols (w&1)*64 .. +63.
// -------------------------------------------------------------------------
extern __shared__ uint32_t dsm[];

__global__ void __launch_bounds__(NTHREADS, 1)
gemm_scatter_mma(const float* __restrict__ x,
                 const void* __restrict__ ei_raw,
                 const float* __restrict__ ef,
                 const float* __restrict__ W,
                 float* __restrict__ out)
{
    __shared__ int s_src[TM];
    __shared__ int s_dst[TM];

    uint32_t* sA  = dsm;                     // [TM][A_STRIDE]   half2 words
    uint32_t* sWp = dsm + SMEM_A_WORDS;      // [KW][WP_STRIDE]  half2 (k,k+1) per n

    const int tid = threadIdx.x;
    const int wid = tid >> 5;
    const int lane = tid & 31;
    const int e0 = blockIdx.x * TM;

    if (tid < TM) {
        int s, d;
        if (g_idx64) {
            const long long* ei = (const long long*)ei_raw;
            s = (int)ei[e0 + tid];
            d = (int)ei[E_TOTAL + e0 + tid];
        } else {
            const int* ei = (const int*)ei_raw;
            s = ei[e0 + tid];
            d = ei[E_TOTAL + e0 + tid];
        }
        s_src[tid] = clampi(s, 0, N_NODES - 1);
        s_dst[tid] = clampi(d, 0, N_NODES - 1);
        atomicAdd(&g_cnt[s_dst[tid]], 1.0f);
    }
    __syncthreads();

    // ---- stage A: 256 rows x 192 cols as half2; one float4 -> uint2 ----
    #pragma unroll 2
    for (int idx = tid; idx < TM * 48; idx += NTHREADS) {
        int e = idx / 48, q = idx - e * 48;          // q: float4 index 0..47
        float4 v;
        if (q < 32) v = ((const float4*)(x + (size_t)s_src[e] * D_NODE))[q];
        else        v = ((const float4*)(ef + (size_t)(e0 + e) * D_EDGE))[q - 32];
        uint2 t;
        t.x = pack2(v.x, v.y);
        t.y = pack2(v.z, v.w);
        *(uint2*)(sA + e * A_STRIDE + q * 2) = t;
    }
    // ---- stage W as k-pairs: sWp[kp][n] = half2(W[2kp][n], W[2kp+1][n]) ----
    #pragma unroll 2
    for (int idx = tid; idx < KW * 32; idx += NTHREADS) {
        int kp = idx >> 5, nq = idx & 31;            // nq*4 = n0
        float4 v0 = ((const float4*)(W + (size_t)(2 * kp)     * D_OUT))[nq];
        float4 v1 = ((const float4*)(W + (size_t)(2 * kp + 1) * D_OUT))[nq];
        uint4 t;
        t.x = pack2(v0.x, v1.x);
        t.y = pack2(v0.y, v1.y);
        t.z = pack2(v0.z, v1.z);
        t.w = pack2(v0.w, v1.w);
        *(uint4*)(sWp + kp * WP_STRIDE + nq * 4) = t;
    }
    __syncthreads();

    const int rowband = (wid >> 1) * 32;
    const int colh = (wid & 1) * 64;
    const int g  = lane >> 2;      // 0..7
    const int tg = lane & 3;       // 0..3

    float acc[2][8][4];
#pragma unroll
    for (int m = 0; m < 2; m++)
#pragma unroll
        for (int nt = 0; nt < 8; nt++)
#pragma unroll
            for (int c = 0; c < 4; c++) acc[m][nt][c] = 0.0f;

    // ---- 12 k-steps of m16n8k16 (8 half2 words per step) ----
#pragma unroll
    for (int s = 0; s < 12; s++) {
        const int kp0 = s * 8;
        const uint32_t* pa = sA + (rowband + g) * A_STRIDE + kp0 + tg;
        uint32_t a[2][4];
        a[0][0] = pa[0];
        a[0][1] = pa[8 * A_STRIDE];
        a[0][2] = pa[4];
        a[0][3] = pa[8 * A_STRIDE + 4];
        a[1][0] = pa[16 * A_STRIDE];
        a[1][1] = pa[24 * A_STRIDE];
        a[1][2] = pa[16 * A_STRIDE + 4];
        a[1][3] = pa[24 * A_STRIDE + 4];

        const uint32_t* pb0 = sWp + (kp0 + tg) * WP_STRIDE + colh + g;
        const uint32_t* pb1 = pb0 + 4 * WP_STRIDE;
#pragma unroll
        for (int nt = 0; nt < 8; nt++) {
            uint32_t b0 = pb0[nt * 8];
            uint32_t b1 = pb1[nt * 8];
            mma_f16(acc[0][nt], a[0][0], a[0][1], a[0][2], a[0][3], b0, b1);
            mma_f16(acc[1][nt], a[1][0], a[1][1], a[1][2], a[1][3], b0, b1);
        }
    }

    // ---- scatter-add epilogue (direct, as R12) ----
#pragma unroll
    for (int m = 0; m < 2; m++) {
        int r = rowband + m * 16 + g;
        float* p0 = out + (size_t)s_dst[r] * D_OUT;
        float* p1 = out + (size_t)s_dst[r + 8] * D_OUT;
        int cb = colh + 2 * tg;
#pragma unroll
        for (int nt = 0; nt < 8; nt++) {
            atomicAdd(p0 + cb + nt * 8,     acc[m][nt][0]);
            atomicAdd(p0 + cb + nt * 8 + 1, acc[m][nt][1]);
            atomicAdd(p1 + cb + nt * 8,     acc[m][nt][2]);
            atomicAdd(p1 + cb + nt * 8 + 1, acc[m][nt][3]);
        }
    }
}

// -------------------------------------------------------------------------
__global__ void finalize_kernel(float* __restrict__ out, const float* __restrict__ b) {
    int i = blockIdx.x * blockDim.x + threadIdx.x;
    if (i >= N_NODES * D_OUT) return;
    int node = i >> 7;
    float c = g_cnt[node];
    float v = out[i];
    out[i] = (c > 0.0f) ? (v / c + b[i & (D_OUT - 1)]) : 0.0f;
}

// -------------------------------------------------------------------------
extern "C" void kernel_launch(void* const* d_in, const int* in_sizes, int n_in,
                              void* d_out, int out_size)
{
    const float* x  = (const float*)d_in[0];
    const void*  ei = d_in[1];
    const float* ef = (const float*)d_in[2];
    const float* W  = (const float*)d_in[3];
    const float* b  = (const float*)d_in[4];
    float* out = (float*)d_out;

    cudaFuncSetAttribute(gemm_scatter_mma,
                         cudaFuncAttributeMaxDynamicSharedMemorySize, SMEM_BYTES);

    const int total = N_NODES * D_OUT;
    zero_kernel<<<(total + 255) / 256, 256>>>(out, (const unsigned*)ei);
    gemm_scatter_mma<<<E_TOTAL / TM, NTHREADS, SMEM_BYTES>>>(x, ei, ef, W, out);
    finalize_kernel<<<(total + 255) / 256, 256>>>(out, b);
}

// round 17
// speedup vs baseline: 1.6679x; 1.2706x over previous
#include <cuda_runtime.h>
#include <cuda_fp16.h>
#include <cstdint>

#define N_NODES 10000
#define E_TOTAL 640000
#define D_NODE 128
#define D_EDGE 64
#define D_IN 192
#define D_OUT 128

#define TM 128              // edges per tile
#define NTHREADS 512        // 16 warps
#define GRID 148            // persistent CTAs (1/SM)
#define NTILES (E_TOTAL / TM)   // 5000
#define KW 96               // K in half2 words (192 halves)
#define A_STRIDE 100        // words; mod 32 = 4 -> conflict-free A frags
#define WP_STRIDE 136       // words; mod 32 = 8 -> conflict-free B frags

#define A_BUF_WORDS (TM * A_STRIDE)             // 12800 (51.2 KB)
#define SMEM_W_OFF  (2 * A_BUF_WORDS)           // 25600
#define SMEM_WORDS  (SMEM_W_OFF + KW * WP_STRIDE)   // 38656
#define SMEM_BYTES  (SMEM_WORDS * 4)            // 154624

__device__ float g_cnt[N_NODES];
__device__ int   g_idx64;

__device__ __forceinline__ void mma_f16(float* d, uint32_t a0, uint32_t a1,
                                        uint32_t a2, uint32_t a3,
                                        uint32_t b0, uint32_t b1) {
    asm volatile(
        "mma.sync.aligned.m16n8k16.row.col.f32.f16.f16.f32 "
        "{%0,%1,%2,%3}, {%4,%5,%6,%7}, {%8,%9}, {%0,%1,%2,%3};"
        : "+f"(d[0]), "+f"(d[1]), "+f"(d[2]), "+f"(d[3])
        : "r"(a0), "r"(a1), "r"(a2), "r"(a3), "r"(b0), "r"(b1));
}
__device__ __forceinline__ uint32_t pack2(float lo, float hi) {
    __half2 h = __floats2half2_rn(lo, hi);
    return *(uint32_t*)&h;
}
__device__ __forceinline__ int clampi(int v, int lo, int hi) {
    return v < lo ? lo : (v > hi ? hi : v);
}

// -------------------------------------------------------------------------
__global__ void zero_kernel(float* __restrict__ out, const unsigned* __restrict__ eiw) {
    int i = blockIdx.x * blockDim.x + threadIdx.x;
    if (i < N_NODES * D_OUT) out[i] = 0.0f;
    if (i < N_NODES) g_cnt[i] = 0.0f;
    if (blockIdx.x == 0 && threadIdx.x == 0) {
        int is64 = 1;
        #pragma unroll 1
        for (int k = 0; k < 64; k++) {
            unsigned hi = eiw[2 * k + 1];
            if (hi != 0u && hi != 0xFFFFFFFFu) { is64 = 0; break; }
        }
        g_idx64 = is64;
    }
}

// -------------------------------------------------------------------------
// Persistent fused gather + fp16 mma GEMM + scatter.
// 148 CTAs, each loops over tiles of 128 edges; W staged once; A double-
// buffered with register-prefetch so gather latency hides under MMA.
// Warp w: rows (w>>1)*16 .. +15, cols (w&1)*64 .. +63.
// -------------------------------------------------------------------------
extern __shared__ uint32_t dsm[];

__global__ void __launch_bounds__(NTHREADS, 1)
gemm_scatter_mma(const float* __restrict__ x,
                 const void* __restrict__ ei_raw,
                 const float* __restrict__ ef,
                 const float* __restrict__ W,
                 float* __restrict__ out)
{
    __shared__ int s_src[2][TM];
    __shared__ int s_dst[2][TM];

    uint32_t* sWp = dsm + SMEM_W_OFF;        // [KW][WP_STRIDE]

    const int tid = threadIdx.x;
    const int wid = tid >> 5;
    const int lane = tid & 31;

    const int rowband = (wid >> 1) * 16;
    const int colh = (wid & 1) * 64;
    const int lq = lane >> 2;      // 0..7
    const int lr = lane & 3;       // 0..3

    // ---- stage W once: sWp[kp][n] = half2(W[2kp][n], W[2kp+1][n]) ----
    #pragma unroll 2
    for (int idx = tid; idx < KW * 32; idx += NTHREADS) {
        int kp = idx >> 5, nq = idx & 31;
        float4 v0 = ((const float4*)(W + (size_t)(2 * kp)     * D_OUT))[nq];
        float4 v1 = ((const float4*)(W + (size_t)(2 * kp + 1) * D_OUT))[nq];
        uint4 t;
        t.x = pack2(v0.x, v1.x);
        t.y = pack2(v0.y, v1.y);
        t.z = pack2(v0.z, v1.z);
        t.w = pack2(v0.w, v1.w);
        *(uint4*)(sWp + kp * WP_STRIDE + nq * 4) = t;
    }

    const int is64 = g_idx64;
    const int t0 = blockIdx.x;

    // ---- prologue: stage indices + A for first tile into buffer 0 ----
    if (t0 < NTILES && tid < TM) {
        int e = t0 * TM + tid;
        int s, d;
        if (is64) {
            const long long* ei = (const long long*)ei_raw;
            s = (int)ei[e];
            d = (int)ei[E_TOTAL + e];
        } else {
            const int* ei = (const int*)ei_raw;
            s = ei[e];
            d = ei[E_TOTAL + e];
        }
        s_src[0][tid] = clampi(s, 0, N_NODES - 1);
        s_dst[0][tid] = clampi(d, 0, N_NODES - 1);
        atomicAdd(&g_cnt[s_dst[0][tid]], 1.0f);
    }
    __syncthreads();
    if (t0 < NTILES) {
        uint32_t* sA = dsm;                  // buffer 0
        #pragma unroll
        for (int j = 0; j < 12; j++) {
            int linear = j * NTHREADS + tid;
            int e = linear / 48, q = linear - e * 48;
            float4 v;
            if (q < 32) v = ((const float4*)(x + (size_t)s_src[0][e] * D_NODE))[q];
            else        v = ((const float4*)(ef + (size_t)(t0 * TM + e) * D_EDGE))[q - 32];
            uint2 p2;
            p2.x = pack2(v.x, v.y);
            p2.y = pack2(v.z, v.w);
            *(uint2*)(sA + e * A_STRIDE + q * 2) = p2;
        }
    }

    int p = 0;
    #pragma unroll 1
    for (int t = t0; t < NTILES; t += GRID) {
        const int tn = t + GRID;
        const int pn = p ^ 1;

        // stage next tile's indices (visible after the sync below)
        if (tn < NTILES && tid < TM) {
            int e = tn * TM + tid;
            int s, d;
            if (is64) {
                const long long* ei = (const long long*)ei_raw;
                s = (int)ei[e];
                d = (int)ei[E_TOTAL + e];
            } else {
                const int* ei = (const int*)ei_raw;
                s = ei[e];
                d = ei[E_TOTAL + e];
            }
            s_src[pn][tid] = clampi(s, 0, N_NODES - 1);
            s_dst[pn][tid] = clampi(d, 0, N_NODES - 1);
            atomicAdd(&g_cnt[s_dst[pn][tid]], 1.0f);
        }
        __syncthreads();   // A(t,p) STS + idx(tn,pn) visible; buf pn free

        // ---- prefetch next tile's A into registers (latency hides under MMA) ----
        float4 v[12];
        if (tn < NTILES) {
            #pragma unroll
            for (int j = 0; j < 12; j++) {
                int linear = j * NTHREADS + tid;
                int e = linear / 48, q = linear - e * 48;
                if (q < 32) v[j] = ((const float4*)(x + (size_t)s_src[pn][e] * D_NODE))[q];
                else        v[j] = ((const float4*)(ef + (size_t)(tn * TM + e) * D_EDGE))[q - 32];
            }
        }

        // ---- compute current tile ----
        const uint32_t* sA = dsm + p * A_BUF_WORDS;
        float acc[8][4];
        #pragma unroll
        for (int nt = 0; nt < 8; nt++)
            #pragma unroll
            for (int c = 0; c < 4; c++) acc[nt][c] = 0.0f;

        #pragma unroll
        for (int s = 0; s < 12; s++) {
            const int kp0 = s * 8;
            const uint32_t* pa = sA + (rowband + lq) * A_STRIDE + kp0 + lr;
            uint32_t a0 = pa[0];
            uint32_t a1 = pa[8 * A_STRIDE];
            uint32_t a2 = pa[4];
            uint32_t a3 = pa[8 * A_STRIDE + 4];

            const uint32_t* pb0 = sWp + (kp0 + lr) * WP_STRIDE + colh + lq;
            const uint32_t* pb1 = pb0 + 4 * WP_STRIDE;
            #pragma unroll
            for (int nt = 0; nt < 8; nt++) {
                mma_f16(acc[nt], a0, a1, a2, a3, pb0[nt * 8], pb1[nt * 8]);
            }
        }

        // ---- store prefetched A into the other buffer ----
        if (tn < NTILES) {
            uint32_t* sAn = dsm + pn * A_BUF_WORDS;
            #pragma unroll
            for (int j = 0; j < 12; j++) {
                int linear = j * NTHREADS + tid;
                int e = linear / 48, q = linear - e * 48;
                uint2 p2;
                p2.x = pack2(v[j].x, v[j].y);
                p2.y = pack2(v[j].z, v[j].w);
                *(uint2*)(sAn + e * A_STRIDE + q * 2) = p2;
            }
        }

        // ---- scatter-add epilogue ----
        {
            int r = rowband + lq;
            float* p0 = out + (size_t)s_dst[p][r] * D_OUT;
            float* p1 = out + (size_t)s_dst[p][r + 8] * D_OUT;
            int cb = colh + 2 * lr;
            #pragma unroll
            for (int nt = 0; nt < 8; nt++) {
                atomicAdd(p0 + cb + nt * 8,     acc[nt][0]);
                atomicAdd(p0 + cb + nt * 8 + 1, acc[nt][1]);
                atomicAdd(p1 + cb + nt * 8,     acc[nt][2]);
                atomicAdd(p1 + cb + nt * 8 + 1, acc[nt][3]);
            }
        }
        p ^= 1;
    }
}

// -------------------------------------------------------------------------
__global__ void finalize_kernel(float* __restrict__ out, const float* __restrict__ b) {
    int i = blockIdx.x * blockDim.x + threadIdx.x;
    if (i >= N_NODES * D_OUT) return;
    int node = i >> 7;
    float c = g_cnt[node];
    float v = out[i];
    out[i] = (c > 0.0f) ? (v / c + b[i & (D_OUT - 1)]) : 0.0f;
}

// -------------------------------------------------------------------------
extern "C" void kernel_launch(void* const* d_in, const int* in_sizes, int n_in,
                              void* d_out, int out_size)
{
    const float* x  = (const float*)d_in[0];
    const void*  ei = d_in[1];
    const float* ef = (const float*)d_in[2];
    const float* W  = (const float*)d_in[3];
    const float* b  = (const float*)d_in[4];
    float* out = (float*)d_out;

    cudaFuncSetAttribute(gemm_scatter_mma,
                         cudaFuncAttributeMaxDynamicSharedMemorySize, SMEM_BYTES);

    const int total = N_NODES * D_OUT;
    zero_kernel<<<(total + 255) / 256, 256>>>(out, (const unsigned*)ei);
    gemm_scatter_mma<<<GRID, NTHREADS, SMEM_BYTES>>>(x, ei, ef, W, out);
    finalize_kernel<<<(total + 255) / 256, 256>>>(out, b);
}